// round 8
// baseline (speedup 1.0000x reference)
#include <cuda_runtime.h>
#include <cuda_bf16.h>
#include <math.h>

// Dimensions (fixed by the problem)
#define B_ROWS 512
#define D_IN 5
#define H_DIM 128
#define VF_DIM 256
#define L_SEG 62        // LS-1
#define LAB 10
#define NSTEP 20
#define RB 4            // rows per CTA
#define NCTA (B_ROWS / RB)   // 128
#define NTHR 1024

typedef unsigned long long ull_t;

// Precomputed global scratch (device globals: no allocation allowed)
__device__ float g_W1t[H_DIM * VF_DIM];          // [k=128][c=256]
__device__ float g_W2t[VF_DIM * VF_DIM];         // [k=256][c=256]
__device__ float g_Wm[32 * VF_DIM * H_DIM];      // [idx][v=256][h=128]  4 MB
__device__ float g_bm[32 * H_DIM];               // [idx][h]
__device__ float g_delta[32];                    // interval widths
__device__ int   g_idx[2 * NSTEP];               // 0-based logsig row per eval

// ---------------------------------------------------------------------------
// f32x2 packed-FMA helpers (sm_103a FFMA2 — PTX-only)
// ---------------------------------------------------------------------------
__device__ __forceinline__ ull_t dup2(float x) {
    ull_t r;
    unsigned int u = __float_as_uint(x);
    asm("mov.b64 %0, {%1, %1};" : "=l"(r) : "r"(u));
    return r;
}
__device__ __forceinline__ void fma2(ull_t& acc, ull_t a, ull_t b) {
    asm("fma.rn.f32x2 %0, %1, %2, %0;" : "+l"(acc) : "l"(a), "l"(b));
}
__device__ __forceinline__ void unpk(ull_t v, float& a, float& b) {
    unsigned int lo, hi;
    asm("mov.b64 {%0, %1}, %2;" : "=r"(lo), "=r"(hi) : "l"(v));
    a = __uint_as_float(lo);
    b = __uint_as_float(hi);
}

// ---------------------------------------------------------------------------
// Setup kernel (merged prep + wmeff).  grid = 160 x 256.
// ---------------------------------------------------------------------------
__global__ void __launch_bounds__(256) setup_kernel(
    const float* __restrict__ ts,
    const float* __restrict__ intervals,
    const float* __restrict__ W1,      // [256][128]
    const float* __restrict__ W2,      // [256][256]
    const float* __restrict__ logsig,  // [32][63]
    const float* __restrict__ Wm,      // [7936][256]
    const float* __restrict__ bm)      // [7936]
{
    if (blockIdx.x < 128) {
        __shared__ float ls[32 * L_SEG];
        int h = blockIdx.x;
        int v = threadIdx.x;

        for (int i = threadIdx.x; i < 32 * L_SEG; i += blockDim.x) {
            int row = i / L_SEG, l = i % L_SEG;
            ls[i] = logsig[row * 63 + l + 1];
        }
        __syncthreads();

        float acc[32];
        #pragma unroll
        for (int i = 0; i < 32; i++) acc[i] = 0.0f;

        for (int l = 0; l < L_SEG; l++) {
            float w = __ldg(&Wm[(h * L_SEG + l) * VF_DIM + v]);
            #pragma unroll
            for (int i = 0; i < 32; i++) acc[i] += w * ls[i * L_SEG + l];
        }
        #pragma unroll
        for (int i = 0; i < 32; i++)
            g_Wm[i * (VF_DIM * H_DIM) + v * H_DIM + h] = acc[i];

        if (threadIdx.x < 32) {
            int i = threadIdx.x;
            float s = 0.0f;
            for (int l = 0; l < L_SEG; l++)
                s += __ldg(&bm[h * L_SEG + l]) * ls[i * L_SEG + l];
            g_bm[i * H_DIM + h] = s;
        }
    } else {
        int b = blockIdx.x - 128;              // 0..31
        int gtid = b * 256 + threadIdx.x;      // 0..8191
        int gsz  = 32 * 256;

        for (int i = gtid; i < H_DIM * VF_DIM; i += gsz) {
            int k = i >> 8, c = i & 255;
            g_W1t[i] = W1[c * H_DIM + k];
        }
        for (int i = gtid; i < VF_DIM * VF_DIM; i += gsz) {
            int k = i >> 8, c = i & 255;
            g_W2t[i] = W2[c * VF_DIM + k];
        }
        if (b == 0) {
            if (threadIdx.x < 32)
                g_delta[threadIdx.x] = intervals[threadIdx.x + 1] - intervals[threadIdx.x];
            if (threadIdx.x < 2 * NSTEP) {
                // Replicate reference fp32 exactly
                float t0 = ts[0];
                float dt = (ts[32] - t0) / 20.0f;
                int i = threadIdx.x >> 1;
                float t = t0 + (float)i * dt;
                if (threadIdx.x & 1) t = t + dt;
                int cnt = 0;
                #pragma unroll
                for (int j = 1; j <= 32; j++) cnt += (intervals[j] < t) ? 1 : 0;
                int idx = cnt + 1;
                idx = max(1, min(idx, 32));
                g_idx[threadIdx.x] = idx - 1;
            }
        }
    }
}

// ---------------------------------------------------------------------------
// Persistent integration kernel: 128 CTAs x 1024 threads, 4 rows per CTA.
// 2-col x 4-row blocking with row-pair f32x2 packing; split-K 8 (L1/L2),
// split-K 16 (L3); cross-phase weight prefetch; pipelined global weights.
// ---------------------------------------------------------------------------
#define SMEM_FLOATS (32768 + 512 + 512 + 512 + 1024 + 1024 + 8192)  // 178 KB

__global__ void __launch_bounds__(NTHR, 1)
integrate_kernel(const float* __restrict__ x0,     // [512][5]
                 const float* __restrict__ W_in,   // [128][5]
                 const float* __restrict__ b_in,   // [128]
                 const float* __restrict__ b1,     // [256]
                 const float* __restrict__ b2,     // [256]
                 const float* __restrict__ W_out,  // [10][128]
                 const float* __restrict__ b_out,  // [10]
                 const float* __restrict__ ts,
                 float* __restrict__ out)          // [512][10]
{
    extern __shared__ __align__(16) float sm[];
    float* W1s  = sm;                    // 32768 : W1t cached [k][c]
    float* y_s  = W1s + 32768;           // 512   : y   [h=128][r=4]
    float* yt_s = y_s + 512;             // 512
    float* k1_s = yt_s + 512;            // 512
    float* h1_s = k1_s + 512;            // 1024  : [c=256][r=4]
    float* h2_s = h1_s + 1024;           // 1024
    float* p_s  = h2_s + 1024;           // 8192  : split-K partials

    const int tid = threadIdx.x;
    const int r0  = blockIdx.x * RB;
    // Layers 1/2: 2 cols x 4 rows; 128 col-pairs x 8 K-slices
    const int cb  = tid & 127;           // col-pair (cols cb*2, cb*2+1)
    const int s   = tid >> 7;            // K-slice (0..7)
    // Layer 3: 2 cols x 4 rows; 64 col-pairs x 16 K-slices
    const int cb3 = tid & 63;
    const int s3  = tid >> 6;

    // Cache W1t into shared memory (float4 copies)
    for (int i = tid; i < 8192; i += NTHR)
        *(float4*)&W1s[i * 4] = *(const float4*)&g_W1t[i * 4];

    // y0 = x0 @ W_in^T + b_in   (one (h, r) per thread, tid < 512)
    if (tid < 512) {
        int h = tid >> 2, r = tid & 3;
        float acc = __ldg(&b_in[h]);
        #pragma unroll
        for (int d = 0; d < D_IN; d++)
            acc += __ldg(&x0[(r0 + r) * D_IN + d]) * __ldg(&W_in[h * D_IN + d]);
        y_s[tid] = acc;
    }
    const float dt = (ts[32] - ts[0]) / 20.0f;
    __syncthreads();

    // Fixed per-thread weight base pointers
    const float* wp1 = W1s   + (s * 16) * VF_DIM + cb * 2;   // layer1, smem
    const float* wp2 = g_W2t + (s * 32) * VF_DIM + cb * 2;   // layer2, global

    for (int step = 0; step < NSTEP; step++) {
        #pragma unroll 1
        for (int phase = 0; phase < 2; phase++) {
            const float* in_s = phase ? yt_s : y_s;
            const int kt = g_idx[2 * step + phase];
            const float* wp3 = g_Wm + kt * (VF_DIM * H_DIM) + (s3 * 16) * H_DIM + cb3 * 2;

            float2 w2buf[4];
            float2 w3buf[4];

            // ==== Layer 1 GEMM: K=128, 8 slices x 16 iters, smem weights ====
            {
                const float* ap = in_s + (s * 16) * 4;
                ull_t a00 = 0ull, a01 = 0ull, a10 = 0ull, a11 = 0ull;
                #pragma unroll
                for (int k = 0; k < 16; k++) {
                    float2 w = *(const float2*)(wp1 + k * VF_DIM);
                    ulonglong2 av = *(const ulonglong2*)(ap + k * 4);
                    ull_t d0 = dup2(w.x), d1 = dup2(w.y);
                    fma2(a00, d0, av.x); fma2(a01, d0, av.y);
                    fma2(a10, d1, av.x); fma2(a11, d1, av.y);
                }
                ulonglong2* pp = (ulonglong2*)(p_s + s * 1024 + cb * 8);
                pp[0] = make_ulonglong2(a00, a01);
                pp[1] = make_ulonglong2(a10, a11);
            }
            // Prefetch layer-2 weights (L2 latency hides behind barrier+reduce)
            #pragma unroll
            for (int j = 0; j < 4; j++)
                w2buf[j] = *(const float2*)(wp2 + j * VF_DIM);
            __syncthreads();

            // ==== Reduce 1 (1024 threads, one (c,r) each): bias + relu ====
            {
                int c = tid >> 2;
                float a = 0.f;
                #pragma unroll
                for (int ss = 0; ss < 8; ss++)
                    a += p_s[ss * 1024 + tid];
                h1_s[tid] = fmaxf(a + __ldg(&b1[c]), 0.f);
            }
            __syncthreads();

            // ==== Layer 2 GEMM: K=256, 8 slices x 32 iters, pipelined LDG ====
            {
                const float* ap = h1_s + (s * 32) * 4;
                ull_t a00 = 0ull, a01 = 0ull, a10 = 0ull, a11 = 0ull;
                #pragma unroll
                for (int kb = 0; kb < 32; kb += 4) {
                    #pragma unroll
                    for (int j = 0; j < 4; j++) {
                        float2 wn = w2buf[j];
                        int nk = kb + 4 + j;
                        if (nk < 32)                  // compile-time resolved
                            wn = *(const float2*)(wp2 + nk * VF_DIM);
                        float2 w = w2buf[j];
                        ulonglong2 av = *(const ulonglong2*)(ap + (kb + j) * 4);
                        ull_t d0 = dup2(w.x), d1 = dup2(w.y);
                        fma2(a00, d0, av.x); fma2(a01, d0, av.y);
                        fma2(a10, d1, av.x); fma2(a11, d1, av.y);
                        w2buf[j] = wn;
                    }
                }
                ulonglong2* pp = (ulonglong2*)(p_s + s * 1024 + cb * 8);
                pp[0] = make_ulonglong2(a00, a01);
                pp[1] = make_ulonglong2(a10, a11);
            }
            // Prefetch layer-3 weights
            #pragma unroll
            for (int j = 0; j < 4; j++)
                w3buf[j] = *(const float2*)(wp3 + j * H_DIM);
            __syncthreads();

            // ==== Reduce 2 (1024 threads): bias + tanh ====
            {
                int c = tid >> 2;
                float a = 0.f;
                #pragma unroll
                for (int ss = 0; ss < 8; ss++)
                    a += p_s[ss * 1024 + tid];
                h2_s[tid] = tanhf(a + __ldg(&b2[c]));
            }
            __syncthreads();

            // ==== Layer 3 GEMM: C=128, 16 slices x 16 iters, pipelined LDG ====
            {
                const float* ap = h2_s + (s3 * 16) * 4;
                ull_t a00 = 0ull, a01 = 0ull, a10 = 0ull, a11 = 0ull;
                #pragma unroll
                for (int kb = 0; kb < 16; kb += 4) {
                    #pragma unroll
                    for (int j = 0; j < 4; j++) {
                        float2 wn = w3buf[j];
                        int nk = kb + 4 + j;
                        if (nk < 16)
                            wn = *(const float2*)(wp3 + nk * H_DIM);
                        float2 w = w3buf[j];
                        ulonglong2 av = *(const ulonglong2*)(ap + (kb + j) * 4);
                        ull_t d0 = dup2(w.x), d1 = dup2(w.y);
                        fma2(a00, d0, av.x); fma2(a01, d0, av.y);
                        fma2(a10, d1, av.x); fma2(a11, d1, av.y);
                        w3buf[j] = wn;
                    }
                }
                ulonglong2* pp = (ulonglong2*)(p_s + s3 * 512 + cb3 * 8);
                pp[0] = make_ulonglong2(a00, a01);
                pp[1] = make_ulonglong2(a10, a11);
            }
            __syncthreads();

            // ==== Reduce 3 + Heun (tid < 512, one (h,r) each) ====
            if (tid < 512) {
                int h = tid >> 2;
                float a = 0.f;
                #pragma unroll
                for (int ss = 0; ss < 16; ss++)
                    a += p_s[ss * 512 + tid];
                float dl  = g_delta[kt];
                float bmv = g_bm[kt * H_DIM + h];
                float d = (a + bmv) / dl;
                if (phase == 0) {
                    k1_s[tid] = d;
                    yt_s[tid] = y_s[tid] + dt * d;
                } else {
                    y_s[tid] = y_s[tid] + 0.5f * dt * (k1_s[tid] + d);
                }
            }
            __syncthreads();
        }
    }

    // ---- Output: softmax(y @ W_out^T + b_out), 4 rows x 10 labels ----
    if (tid < RB * LAB) {
        int lab = tid % LAB, r = tid / LAB;
        float acc = __ldg(&b_out[lab]);
        for (int k = 0; k < H_DIM; k++)
            acc += y_s[k * RB + r] * __ldg(&W_out[lab * H_DIM + k]);
        h1_s[r * LAB + lab] = acc;
    }
    __syncthreads();
    if (tid < RB) {
        int r = tid;
        float mx = -1e30f;
        #pragma unroll
        for (int l = 0; l < LAB; l++) mx = fmaxf(mx, h1_s[r * LAB + l]);
        float e[LAB]; float sum = 0.f;
        #pragma unroll
        for (int l = 0; l < LAB; l++) { e[l] = expf(h1_s[r * LAB + l] - mx); sum += e[l]; }
        #pragma unroll
        for (int l = 0; l < LAB; l++) out[(r0 + r) * LAB + l] = e[l] / sum;
    }
}

// ---------------------------------------------------------------------------
extern "C" void kernel_launch(void* const* d_in, const int* in_sizes, int n_in,
                              void* d_out, int out_size)
{
    const float* ts        = (const float*)d_in[0];
    const float* logsig    = (const float*)d_in[1];
    const float* x0        = (const float*)d_in[2];
    const float* intervals = (const float*)d_in[3];
    const float* W_vf1     = (const float*)d_in[4];
    const float* b_vf1     = (const float*)d_in[5];
    const float* W_vf2     = (const float*)d_in[6];
    const float* b_vf2     = (const float*)d_in[7];
    const float* W_m       = (const float*)d_in[8];
    const float* b_m       = (const float*)d_in[9];
    const float* W_in      = (const float*)d_in[10];
    const float* b_in      = (const float*)d_in[11];
    const float* W_out     = (const float*)d_in[12];
    const float* b_out     = (const float*)d_in[13];
    float* out = (float*)d_out;

    size_t smem_bytes = SMEM_FLOATS * sizeof(float);  // 178176 B
    cudaFuncSetAttribute(integrate_kernel,
                         cudaFuncAttributeMaxDynamicSharedMemorySize,
                         (int)smem_bytes);

    setup_kernel<<<160, 256>>>(ts, intervals, W_vf1, W_vf2, logsig, W_m, b_m);
    integrate_kernel<<<NCTA, NTHR, smem_bytes>>>(x0, W_in, b_in, b_vf1, b_vf2,
                                                 W_out, b_out, ts, out);
}